// round 8
// baseline (speedup 1.0000x reference)
#include <cuda_runtime.h>
#include <cuda_bf16.h>

// Gemma4VisionPooler: 2x2 segment-mean pool (B=16, L=4096 -> 1024, H=1152) * sqrt(H)
// R6: pool_kernel untouched (56.6us @ 6.2TB/s DRAM = mixed-stream roofline).
// Preamble slimmed: scatter does 2 lean global passes (pass 2 hits L2),
// mask counter uses racing plain stores instead of 65K atomicAdds.

#define BATCH  16
#define LIN    4096
#define HID    1152
#define OUTLEN 1024
#define KPOOL  2          // sqrt(LIN/OUTLEN)
#define SLOTS  4          // k^2 rows per segment
#define H4     (HID / 4)  // 288 float4 per row
#define NSEG   (BATCH * OUTLEN)
#define STHREADS 1024

// Scratch (allocation-free rule: __device__ globals)
__device__ int  g_cnt[NSEG];    // 1 if any row maps to segment -> mask
__device__ int  g_vcnt[NSEG];   // valid (non-padded) slot cursor
__device__ int4 g_idx4[NSEG];   // packed absolute row ids, -1 = empty

// ---------------------------------------------------------------------------
// Fused index build. One block per batch, 1024 threads.
// Pass 1: dtype detect + max_x (one sweep of the position words).
// Pass 2: decode + scatter (positions now L2-resident).
// ---------------------------------------------------------------------------
__global__ void __launch_bounds__(STHREADS) scatter_kernel(
    const int* __restrict__ p32,
    const unsigned char* __restrict__ pad)
{
    const int b   = blockIdx.x;
    const int tid = threadIdx.x;

    __shared__ int smax32;   // max clamped x under int32 interpretation
    __shared__ int smax64;   // max clamped x under int64 interpretation
    if (tid == 0) { smax32 = 0; smax64 = 0; }

    // reset this batch's scratch region (exclusively owned by this block)
    for (int s = tid; s < OUTLEN; s += STHREADS) {
        const int bs = b * OUTLEN + s;
        g_cnt[bs]  = 0;
        g_vcnt[bs] = 0;
        g_idx4[bs] = make_int4(-1, -1, -1, -1);
    }
    __syncthreads();

    // ---- pass 1: one sweep. int32 view pairs {x,y}; int64 view: row l spans
    // words {xlo,xhi,ylo,yhi}. Detection: int64 odd words are high words
    // (0 or -1); int32 odd words are y coords, somewhere > 0.
    int found = 0;
    int m32 = 0, m64 = 0;
    for (int l = tid; l < LIN; l += STHREADS) {
        // int32 interpretation: pair at 2l
        const long long base2 = ((long long)b * LIN + l) * 2;
        int w0 = p32[base2 + 0];
        int w1 = p32[base2 + 1];
        if (w1 > 0) found = 1;
        int x32 = w0 < 0 ? 0 : w0;
        m32 = max(m32, x32);
        // int64 interpretation: words at 4l (only valid if buffer is 2x bigger;
        // read guarded by same span: words 4l..4l+1 lie within [0, 4*B*L))
        const long long base4 = ((long long)b * LIN + l) * 4;
        int xlo = p32[base4 + 0];
        int xhi = p32[base4 + 1];
        if (xhi > 0) found = 1;        // high word >0 impossible for int64 -> int32
        int x64 = (xhi < 0) ? 0 : (xlo < 0 ? 0 : xlo);
        m64 = max(m64, x64);
    }
    // NOTE: if data is int32, the base4 reads stay inside the buffer only for
    // l < LIN/2; for safety we must not read beyond. Guard: only read int64
    // view for l < LIN (buffer has 2*LIN words if int32, 4*LIN if int64) ->
    // base4+1 max index = 4*(b*LIN+LIN-1)+1 which exceeds an int32 buffer for
    // b = BATCH-1. To stay in-bounds regardless of dtype, int64-view reads are
    // clamped to the first half of each batch's span; x positions repeat
    // row-major so max over half the rows still includes the global max row
    // pattern only if full rows present. Safer: recompute m64 exactly in pass 2
    // after dtype is known. We therefore use m64 from pass 2 instead.
    (void)m64;

    int is32 = __syncthreads_or(found);
    atomicMax(&smax32, m32);   // smem atomic, cheap
    __syncthreads();

    int wseg;
    if (is32) {
        wseg = (smax32 + 1) / KPOOL;
    } else {
        // exact int64 max pass (L2-resident now)
        int mm = 0;
        for (int l = tid; l < LIN; l += STHREADS) {
            const long long w = ((long long)b * LIN + l) * 4;
            int xlo = p32[w + 0], xhi = p32[w + 1];
            int xi = (xhi < 0) ? 0 : (xlo < 0 ? 0 : xlo);
            mm = max(mm, xi);
        }
        atomicMax(&smax64, mm);
        __syncthreads();
        wseg = (smax64 + 1) / KPOOL;
    }

    // ---- pass 2: decode + scatter (positions in L2)
    for (int l = tid; l < LIN; l += STHREADS) {
        int xi, yi;
        if (is32) {
            const long long w = ((long long)b * LIN + l) * 2;
            xi = p32[w + 0];
            yi = p32[w + 1];
        } else {
            const long long w = ((long long)b * LIN + l) * 4;
            int xlo = p32[w + 0], xhi = p32[w + 1];
            int ylo = p32[w + 2], yhi = p32[w + 3];
            xi = (xhi < 0) ? -1 : xlo;
            yi = (yhi < 0) ? -1 : ylo;
        }
        if (xi < 0) xi = 0;
        if (yi < 0) yi = 0;
        int seg = xi / KPOOL + wseg * (yi / KPOOL);
        if (seg < 0) seg = 0;
        if (seg >= OUTLEN) seg = OUTLEN - 1;   // never corrupt scratch
        const int bs = b * OUTLEN + seg;

        g_cnt[bs] = 1;                         // racing stores of 1: benign

        if (!pad[(long long)b * LIN + l]) {    // only non-padded rows contribute
            int slot = atomicAdd(&g_vcnt[bs], 1);
            if (slot < SLOTS)
                ((int*)&g_idx4[bs])[slot] = b * LIN + l;  // absolute row id
        }
    }
}

// ---------------------------------------------------------------------------
// Gather + mean + scale. One block per (batch, segment), 288 threads, each
// thread owns one float4 column. Single LDG.128 of the packed index, then 4
// independent predicated streaming loads. At HBM roofline -- do not touch.
// ---------------------------------------------------------------------------
__global__ void __launch_bounds__(H4) pool_kernel(
    const float4* __restrict__ in,
    float4* __restrict__ out,
    float* __restrict__ mask_out)
{
    const int bs  = blockIdx.x;          // b * OUTLEN + seg
    const int tid = threadIdx.x;

    const int4 idx = g_idx4[bs];         // one LDG.128, uniform across block

    float4 acc = make_float4(0.f, 0.f, 0.f, 0.f);
    float4 v0, v1, v2, v3;
    const bool p0 = idx.x >= 0, p1 = idx.y >= 0, p2 = idx.z >= 0, p3 = idx.w >= 0;
    if (p0) v0 = __ldcs(&in[(long long)idx.x * H4 + tid]);
    if (p1) v1 = __ldcs(&in[(long long)idx.y * H4 + tid]);
    if (p2) v2 = __ldcs(&in[(long long)idx.z * H4 + tid]);
    if (p3) v3 = __ldcs(&in[(long long)idx.w * H4 + tid]);
    if (p0) { acc.x += v0.x; acc.y += v0.y; acc.z += v0.z; acc.w += v0.w; }
    if (p1) { acc.x += v1.x; acc.y += v1.y; acc.z += v1.z; acc.w += v1.w; }
    if (p2) { acc.x += v2.x; acc.y += v2.y; acc.z += v2.z; acc.w += v2.w; }
    if (p3) { acc.x += v3.x; acc.y += v3.y; acc.z += v3.z; acc.w += v3.w; }

    // pooled = sum / k^2, then * sqrt(H) :  sqrt(1152)/4
    const float SCALE = 8.4852813742385702928f;
    acc.x *= SCALE; acc.y *= SCALE; acc.z *= SCALE; acc.w *= SCALE;

    __stcs(&out[(long long)bs * H4 + tid], acc);

    if (mask_out != nullptr && tid == 0)
        mask_out[bs] = (g_cnt[bs] > 0) ? 1.0f : 0.0f;
}

// ---------------------------------------------------------------------------
extern "C" void kernel_launch(void* const* d_in, const int* in_sizes, int n_in,
                              void* d_out, int out_size)
{
    const float*         hs  = (const float*)d_in[0];          // [B, L, H] f32
    const int*           pos = (const int*)d_in[1];            // [B, L, 2] i32 or i64
    const unsigned char* pad = (const unsigned char*)d_in[2];  // [B, L] bool

    float* out = (float*)d_out;

    const long long hs_elems = (long long)BATCH * OUTLEN * HID;
    float* mask_out = nullptr;
    if ((long long)out_size >= hs_elems + (long long)BATCH * OUTLEN)
        mask_out = out + hs_elems;

    scatter_kernel<<<BATCH, STHREADS>>>(pos, pad);
    pool_kernel<<<NSEG, H4>>>((const float4*)hs, (float4*)out, mask_out);
}

// round 10
// speedup vs baseline: 1.0667x; 1.0667x over previous
#include <cuda_runtime.h>
#include <cuda_bf16.h>

// Gemma4VisionPooler: 2x2 segment-mean pool (B=16, L=4096 -> 1024, H=1152) * sqrt(H)
// R7: revert to the R5 structure (63.8us best; all position reads in-bounds).
// Single retained tweak from R6: g_cnt mask via racing plain stores (benign)
// instead of 65K global atomicAdds. Pool kernel byte-identical to the version
// measured at 56.6us / 6.2TB/s DRAM (mixed-stream HBM roofline).

#define BATCH  16
#define LIN    4096
#define HID    1152
#define OUTLEN 1024
#define KPOOL  2          // sqrt(LIN/OUTLEN)
#define SLOTS  4          // k^2 rows per segment
#define H4     (HID / 4)  // 288 float4 per row
#define NSEG   (BATCH * OUTLEN)
#define STHREADS 1024

// Scratch (allocation-free rule: __device__ globals)
__device__ int  g_cnt[NSEG];    // 1 if any row maps to segment -> mask
__device__ int  g_vcnt[NSEG];   // valid (non-padded) slot cursor
__device__ int4 g_idx4[NSEG];   // packed absolute row ids, -1 = empty

// ---------------------------------------------------------------------------
// Fused index build. One block per batch, 1024 threads.
// All reads stay within the int32-pair span [b*L*2, (b+1)*L*2), which is valid
// for BOTH dtypes (int32 buffer has exactly 2 words/row, int64 has 4).
// int64-view decoding indexes words 4l..4l+3 only AFTER dtype is known.
// ---------------------------------------------------------------------------
__global__ void __launch_bounds__(STHREADS) scatter_kernel(
    const int* __restrict__ p32,
    const unsigned char* __restrict__ pad)
{
    const int b   = blockIdx.x;
    const int tid = threadIdx.x;

    __shared__ int sx[LIN];
    __shared__ int sy[LIN];
    __shared__ int smax;
    __shared__ int s_is32;
    if (tid == 0) { smax = 0; s_is32 = 0; }

    // reset this batch's scratch region (exclusively owned by this block)
    for (int s = tid; s < OUTLEN; s += STHREADS) {
        const int bs = b * OUTLEN + s;
        g_cnt[bs]  = 0;
        g_vcnt[bs] = 0;
        g_idx4[bs] = make_int4(-1, -1, -1, -1);
    }
    __syncthreads();

    // dtype detect over this batch's words (int32 view, always in-bounds):
    // int64 layout: odd words are high words (0/-1). int32 layout: odd words
    // are y coords, somewhere > 0.
    {
        int found = 0;
        const int* base = p32 + (long long)b * LIN * 2;
        for (int i = tid * 2 + 1; i < LIN * 2; i += STHREADS * 2)
            if (base[i] > 0) found = 1;
        if (__syncthreads_or(found) && tid == 0) s_is32 = 1;
    }
    __syncthreads();
    const int is32 = s_is32;

    // decode positions once into shared, accumulate max clamped x
    int lmax = 0;
    for (int l = tid; l < LIN; l += STHREADS) {
        int xi, yi;
        if (is32) {
            const long long w = ((long long)b * LIN + l) * 2;
            xi = p32[w + 0];
            yi = p32[w + 1];
        } else {
            const long long w = ((long long)b * LIN + l) * 4;
            int xlo = p32[w + 0], xhi = p32[w + 1];
            int ylo = p32[w + 2], yhi = p32[w + 3];
            xi = (xhi < 0) ? -1 : xlo;
            yi = (yhi < 0) ? -1 : ylo;
        }
        if (xi < 0) xi = 0;
        if (yi < 0) yi = 0;
        sx[l] = xi;
        sy[l] = yi;
        lmax = max(lmax, xi);
    }
    atomicMax(&smax, lmax);   // shared-mem atomic: cheap
    __syncthreads();
    const int wseg = (smax + 1) / KPOOL;

    // scatter row ids into segment slot lists (16K distinct atomic addresses)
    for (int l = tid; l < LIN; l += STHREADS) {
        int seg = sx[l] / KPOOL + wseg * (sy[l] / KPOOL);
        if (seg < 0) seg = 0;
        if (seg >= OUTLEN) seg = OUTLEN - 1;   // never corrupt scratch
        const int bs = b * OUTLEN + seg;

        g_cnt[bs] = 1;                         // racing stores of 1: benign

        if (!pad[(long long)b * LIN + l]) {    // only non-padded rows contribute
            int slot = atomicAdd(&g_vcnt[bs], 1);
            if (slot < SLOTS)
                ((int*)&g_idx4[bs])[slot] = b * LIN + l;  // absolute row id
        }
    }
}

// ---------------------------------------------------------------------------
// Gather + mean + scale. One block per (batch, segment), 288 threads, each
// thread owns one float4 column. Single LDG.128 of the packed index, then 4
// independent predicated streaming loads. At HBM roofline -- do not touch.
// ---------------------------------------------------------------------------
__global__ void __launch_bounds__(H4) pool_kernel(
    const float4* __restrict__ in,
    float4* __restrict__ out,
    float* __restrict__ mask_out)
{
    const int bs  = blockIdx.x;          // b * OUTLEN + seg
    const int tid = threadIdx.x;

    const int4 idx = g_idx4[bs];         // one LDG.128, uniform across block

    float4 acc = make_float4(0.f, 0.f, 0.f, 0.f);
    float4 v0, v1, v2, v3;
    const bool p0 = idx.x >= 0, p1 = idx.y >= 0, p2 = idx.z >= 0, p3 = idx.w >= 0;
    if (p0) v0 = __ldcs(&in[(long long)idx.x * H4 + tid]);
    if (p1) v1 = __ldcs(&in[(long long)idx.y * H4 + tid]);
    if (p2) v2 = __ldcs(&in[(long long)idx.z * H4 + tid]);
    if (p3) v3 = __ldcs(&in[(long long)idx.w * H4 + tid]);
    if (p0) { acc.x += v0.x; acc.y += v0.y; acc.z += v0.z; acc.w += v0.w; }
    if (p1) { acc.x += v1.x; acc.y += v1.y; acc.z += v1.z; acc.w += v1.w; }
    if (p2) { acc.x += v2.x; acc.y += v2.y; acc.z += v2.z; acc.w += v2.w; }
    if (p3) { acc.x += v3.x; acc.y += v3.y; acc.z += v3.z; acc.w += v3.w; }

    // pooled = sum / k^2, then * sqrt(H) :  sqrt(1152)/4
    const float SCALE = 8.4852813742385702928f;
    acc.x *= SCALE; acc.y *= SCALE; acc.z *= SCALE; acc.w *= SCALE;

    __stcs(&out[(long long)bs * H4 + tid], acc);

    if (mask_out != nullptr && tid == 0)
        mask_out[bs] = (g_cnt[bs] > 0) ? 1.0f : 0.0f;
}

// ---------------------------------------------------------------------------
extern "C" void kernel_launch(void* const* d_in, const int* in_sizes, int n_in,
                              void* d_out, int out_size)
{
    const float*         hs  = (const float*)d_in[0];          // [B, L, H] f32
    const int*           pos = (const int*)d_in[1];            // [B, L, 2] i32 or i64
    const unsigned char* pad = (const unsigned char*)d_in[2];  // [B, L] bool

    float* out = (float*)d_out;

    const long long hs_elems = (long long)BATCH * OUTLEN * HID;
    float* mask_out = nullptr;
    if ((long long)out_size >= hs_elems + (long long)BATCH * OUTLEN)
        mask_out = out + hs_elems;

    scatter_kernel<<<BATCH, STHREADS>>>(pos, pad);
    pool_kernel<<<NSEG, H4>>>((const float4*)hs, (float4*)out, mask_out);
}